// round 4
// baseline (speedup 1.0000x reference)
#include <cuda_runtime.h>
#include <cstdint>

#define B_   128
#define T_   64
#define V_   1024
#define TS_  64
#define H_   512
#define NTOK (B_ * T_)      // 8192
#define G3   (3 * H_)       // 1536
#define IN_  (V_ + TS_)     // 1088

typedef unsigned long long ull;

// ---------------- packed fp32x2 helpers (Blackwell) ----------------
__device__ __forceinline__ ull ffma2(ull a, ull b, ull c) {
    ull d;
    asm("fma.rn.f32x2 %0, %1, %2, %3;" : "=l"(d) : "l"(a), "l"(b), "l"(c));
    return d;
}
__device__ __forceinline__ ull dup2(float a) {
    ull d; unsigned u = __float_as_uint(a);
    asm("mov.b64 %0, {%1, %2};" : "=l"(d) : "r"(u), "r"(u));
    return d;
}
__device__ __forceinline__ float2 u2f(ull a) {
    float2 f; unsigned lo, hi;
    asm("mov.b64 {%0, %1}, %2;" : "=r"(lo), "=r"(hi) : "l"(a));
    f.x = __uint_as_float(lo); f.y = __uint_as_float(hi);
    return f;
}

// ---------------- device scratch ----------------
__device__ float g_xg[NTOK * G3];
__device__ float g_coefA[G3];
__device__ float g_coefC[G3];

// ---------------- kernel 0: fold time-embedding into coefficients ----------------
__global__ void coef_kernel(const float* __restrict__ W_time,
                            const float* __restrict__ b_time,
                            const float* __restrict__ W_ih,
                            const float* __restrict__ b_ih)
{
    int g = blockIdx.x * blockDim.x + threadIdx.x;
    if (g >= G3) return;
    const float* wrow = W_ih + (size_t)g * IN_ + V_;
    float a = 0.f, cc = 0.f;
#pragma unroll 8
    for (int j = 0; j < TS_; j++) {
        float wv = wrow[j];
        a  += W_time[j] * wv;
        cc += b_time[j] * wv;
    }
    g_coefA[g] = a;
    g_coefC[g] = cc + b_ih[g];
}

// ---------------- kernel 1: xg = visit_emb @ W_ih[:, :V]^T (+ epilogue) ----------------
#define BM 128
#define BN 128
#define BK 16
#define AST 132

__global__ __launch_bounds__(256, 2)
void gemm_kernel(const float* __restrict__ A,
                 const float* __restrict__ Bw,
                 const float* __restrict__ interval)
{
    __shared__ float As[BK][AST];
    __shared__ float Bs[BK][AST];

    int tid = threadIdx.x;
    int tx = tid & 15;
    int ty = tid >> 4;
    int rowBase = blockIdx.y * BM;
    int colBase = blockIdx.x * BN;

    int lr = tid >> 2;
    int kq = tid & 3;

    ull acc2[8][4];
#pragma unroll
    for (int i = 0; i < 8; i++)
#pragma unroll
        for (int j = 0; j < 4; j++) acc2[i][j] = 0ull;

    const float* Aptr = A  + (size_t)(rowBase + lr) * V_  + kq * 4;
    const float* Bptr = Bw + (size_t)(colBase + lr) * IN_ + kq * 4;

    for (int kt = 0; kt < V_; kt += BK) {
        float4 a0 = *(const float4*)(Aptr + kt);
        float4 a1 = *(const float4*)(Aptr + (size_t)64 * V_ + kt);
        float4 b0 = *(const float4*)(Bptr + kt);
        float4 b1 = *(const float4*)(Bptr + (size_t)64 * IN_ + kt);

        __syncthreads();
        As[kq*4+0][lr] = a0.x; As[kq*4+1][lr] = a0.y; As[kq*4+2][lr] = a0.z; As[kq*4+3][lr] = a0.w;
        As[kq*4+0][lr+64] = a1.x; As[kq*4+1][lr+64] = a1.y; As[kq*4+2][lr+64] = a1.z; As[kq*4+3][lr+64] = a1.w;
        Bs[kq*4+0][lr] = b0.x; Bs[kq*4+1][lr] = b0.y; Bs[kq*4+2][lr] = b0.z; Bs[kq*4+3][lr] = b0.w;
        Bs[kq*4+0][lr+64] = b1.x; Bs[kq*4+1][lr+64] = b1.y; Bs[kq*4+2][lr+64] = b1.z; Bs[kq*4+3][lr+64] = b1.w;
        __syncthreads();

#pragma unroll
        for (int kk = 0; kk < BK; kk++) {
            const float* ap = &As[kk][ty*8];
            float av[8];
            *(float4*)(av+0) = *(const float4*)(ap);
            *(float4*)(av+4) = *(const float4*)(ap + 4);
            const ull* bp = (const ull*)&Bs[kk][tx*8];
            ull bv0 = bp[0], bv1 = bp[1], bv2 = bp[2], bv3 = bp[3];
#pragma unroll
            for (int i = 0; i < 8; i++) {
                ull a2 = dup2(av[i]);
                acc2[i][0] = ffma2(a2, bv0, acc2[i][0]);
                acc2[i][1] = ffma2(a2, bv1, acc2[i][1]);
                acc2[i][2] = ffma2(a2, bv2, acc2[i][2]);
                acc2[i][3] = ffma2(a2, bv3, acc2[i][3]);
            }
        }
    }

    float ai[8], ca[8], cc[8];
#pragma unroll
    for (int i = 0; i < 8; i++) ai[i] = interval[rowBase + ty*8 + i];
#pragma unroll
    for (int j = 0; j < 8; j++) {
        ca[j] = g_coefA[colBase + tx*8 + j];
        cc[j] = g_coefC[colBase + tx*8 + j];
    }
#pragma unroll
    for (int i = 0; i < 8; i++) {
        size_t rbase = (size_t)(rowBase + ty*8 + i) * G3 + colBase + tx*8;
#pragma unroll
        for (int q = 0; q < 2; q++) {
            float2 v0 = u2f(acc2[i][2*q+0]);
            float2 v1 = u2f(acc2[i][2*q+1]);
            float4 o;
            o.x = v0.x + ai[i] * ca[4*q+0] + cc[4*q+0];
            o.y = v0.y + ai[i] * ca[4*q+1] + cc[4*q+1];
            o.z = v1.x + ai[i] * ca[4*q+2] + cc[4*q+2];
            o.w = v1.y + ai[i] * ca[4*q+3] + cc[4*q+3];
            *(float4*)&g_xg[rbase + 4*q] = o;
        }
    }
}

// ---------------- kernel 2: persistent cluster GRU scan ----------------
// 16-CTA cluster, 512 threads. Warp w of CTA c owns hidden units j0=32c+2w, j0+1
// (6 W_hh rows in registers as f32x2). Per step:
//   poll 256 flags (slot = 16*src_warp + src_cta) >= s-1  -> inputs hb[(s-1)&1] ready
//   matvec (48 FFMA2) -> 5-level shfl reduce -> gates on lanes 0,1
//   lanes 0..15: st.shared::cluster.b64 of (h0,h1) to CTA l's hb[s&1],
//                then SAME LANE st.release flag = s  (sound data->flag ordering)
// No __syncthreads, no mbarriers, no atomics. Monotonic flags, double-buffered h.

__device__ __forceinline__ int hperm(int col) {
    return ((col >> 2) & 3) * 128 + ((col >> 4) << 2) + (col & 3);
}

__device__ __forceinline__ unsigned ld_acq_u32(uint32_t saddr) {
    unsigned v;
    asm volatile("ld.acquire.cluster.shared::cta.u32 %0, [%1];"
                 : "=r"(v) : "r"(saddr) : "memory");
    return v;
}

// all 32 lanes cover slots l, l+32, ..., l+224 (conflict-free stride)
__device__ __forceinline__ void poll_flags(uint32_t fl_u, int l, unsigned target) {
    uint32_t a = fl_u + 4u * (unsigned)l;
    for (;;) {
        unsigned m = ld_acq_u32(a);
#pragma unroll
        for (int k = 1; k < 8; k++) {
            unsigned v = ld_acq_u32(a + 128u * k);
            m = min(m, v);
        }
        if (m >= target) break;
    }
    __syncwarp();
}

__global__ void __launch_bounds__(512, 1)
scan_kernel(const float* __restrict__ W_hh,
            const float* __restrict__ b_hh,
            const int*   __restrict__ lens,
            float*       __restrict__ out)
{
    __shared__ float    hb[2][512];      // permuted layout, double-buffered
    __shared__ unsigned flags[256];      // monotonic step ids per (src warp, src cta)
    __shared__ float    bhh[96];         // biases for this CTA's 32 units (r,z,n)
    __shared__ int      lens_sm[128];

    int tid = threadIdx.x;
    int w = tid >> 5;
    int l = tid & 31;
    uint32_t c;
    asm("mov.u32 %0, %%cluster_ctarank;" : "=r"(c));

    hb[0][tid] = 0.f;
    hb[1][tid] = 0.f;
    if (tid < 256) flags[tid] = 0u;
    if (tid < 128) lens_sm[tid] = lens[tid];
    if (tid < 96) {
        int s = tid >> 5, u = tid & 31;
        bhh[tid] = b_hh[s * H_ + 32 * (int)c + u];
    }
    __syncthreads();
    asm volatile("barrier.cluster.arrive.aligned;" ::: "memory");
    asm volatile("barrier.cluster.wait.aligned;"   ::: "memory");

    // ---- weights to registers ----
    int j0 = 32 * (int)c + 2 * w;
    ull W2[6][8];
#pragma unroll
    for (int s = 0; s < 6; s++) {
        int row = (s < 2) ? (j0 + s) : (s < 4) ? (H_ + j0 + s - 2) : (2 * H_ + j0 + s - 4);
        const ull* wp = (const ull*)(W_hh + (size_t)row * H_ + 16 * l);
#pragma unroll
        for (int k = 0; k < 8; k++) W2[s][k] = wp[k];
    }

    // ---- remote addresses (lane l<16 ships to CTA l) ----
    uint32_t hb_u = (uint32_t)__cvta_generic_to_shared(hb);
    uint32_t fl_u = (uint32_t)__cvta_generic_to_shared(flags);
    uint32_t ra_d = 0, ra_f = 0;
    if (l < 16) {
        uint32_t la_d = hb_u + (uint32_t)(hperm(j0) * 4);          // buffer 0 base
        uint32_t la_f = fl_u + (uint32_t)((16 * w + (int)c) * 4);
        asm("mapa.shared::cluster.u32 %0, %1, %2;" : "=r"(ra_d) : "r"(la_d), "r"(l));
        asm("mapa.shared::cluster.u32 %0, %1, %2;" : "=r"(ra_f) : "r"(la_f), "r"(l));
    }

    // ---- xg prefetch state (gate lanes only) ----
    int pb = 0, pt = 0;
    while (pb < B_ && lens_sm[pb] == 0) pb++;
    float nxr = 0.f, nxz = 0.f, nxn = 0.f;
    if (l < 2 && pb < B_) {
        const float* xp = g_xg + (size_t)((pb << 6) + pt) * G3 + (j0 + l);
        nxr = __ldg(xp); nxz = __ldg(xp + H_); nxn = __ldg(xp + 2 * H_);
    }

    unsigned s = 1;
    for (int b = 0; b < B_; b++) {
        int len = lens_sm[b];
        for (int t = 0; t < len; t++) {
            float xr = nxr, xz = nxz, xn = nxn;

            // prefetch next active step (issued before the poll)
            if (l < 2) {
                pt++;
                while (pb < B_ && pt >= lens_sm[pb]) { pb++; pt = 0; }
                if (pb < B_) {
                    const float* xp = g_xg + (size_t)((pb << 6) + pt) * G3 + (j0 + l);
                    nxr = __ldg(xp); nxz = __ldg(xp + H_); nxn = __ldg(xp + 2 * H_);
                }
            }

            if (s > 1) poll_flags(fl_u, l, s - 1);

            // ---- matvec from registers on hb[(s-1)&1] ----
            const float* hp = hb[(s - 1) & 1];
            ull acc2[6] = {0ull, 0ull, 0ull, 0ull, 0ull, 0ull};
#pragma unroll
            for (int qq = 0; qq < 4; qq++) {
                const ull* hq = (const ull*)(hp + qq * 128 + l * 4);
                ull h01 = hq[0], h23 = hq[1];
#pragma unroll
                for (int r = 0; r < 6; r++) acc2[r] = ffma2(W2[r][2*qq+0], h01, acc2[r]);
#pragma unroll
                for (int r = 0; r < 6; r++) acc2[r] = ffma2(W2[r][2*qq+1], h23, acc2[r]);
            }
            float acc[6];
#pragma unroll
            for (int r = 0; r < 6; r++) { float2 f = u2f(acc2[r]); acc[r] = f.x + f.y; }

#pragma unroll
            for (int off = 16; off > 0; off >>= 1) {
#pragma unroll
                for (int r = 0; r < 6; r++)
                    acc[r] += __shfl_xor_sync(0xffffffffu, acc[r], off);
            }

            float hnew = 0.f;
            if (l < 2) {
                int bidx = 2 * w + l;
                float hold = hp[hperm(j0 + l)];
                float rr = __fdividef(1.f, 1.f + __expf(-(xr + acc[l]     + bhh[bidx])));
                float zz = __fdividef(1.f, 1.f + __expf(-(xz + acc[2 + l] + bhh[32 + bidx])));
                float ag = xn + rr * (acc[4 + l] + bhh[64 + bidx]);
                float nn = 1.f - __fdividef(2.f, __expf(2.f * ag) + 1.f);
                hnew = (1.f - zz) * nn + zz * hold;
            }

            // ---- broadcast: lane l<16 ships pair (h0,h1) to CTA l, then flags it ----
            float h0 = __shfl_sync(0xffffffffu, hnew, 0);
            float h1 = __shfl_sync(0xffffffffu, hnew, 1);
            if (l < 16) {
                ull v;
                unsigned u0 = __float_as_uint(h0), u1 = __float_as_uint(h1);
                asm("mov.b64 %0, {%1, %2};" : "=l"(v) : "r"(u0), "r"(u1));
                uint32_t ra = ra_d + (s & 1) * 2048u;   // dest buffer s&1
                asm volatile("st.shared::cluster.b64 [%0], %1;"
                             :: "r"(ra), "l"(v) : "memory");
                asm volatile("st.release.cluster.shared::cluster.b32 [%0], %1;"
                             :: "r"(ra_f), "r"(s) : "memory");
            }
            s++;
        }

        // hidden after sample b (warp 0 only; producers cannot overwrite this
        // buffer until warp 0 posts its step-s flags, which happens later)
        if (tid < 32) {
            if (s > 1) poll_flags(fl_u, l, s - 1);
            int j = 32 * (int)c + l;
            out[b * H_ + j] = hb[(s - 1) & 1][hperm(j)];
        }
    }

    // keep smem alive while any in-flight remote stores land
    asm volatile("barrier.cluster.arrive.aligned;" ::: "memory");
    asm volatile("barrier.cluster.wait.aligned;"   ::: "memory");
}

// ---------------- launcher ----------------
extern "C" void kernel_launch(void* const* d_in, const int* in_sizes, int n_in,
                              void* d_out, int out_size)
{
    const float* visit_emb = (const float*)d_in[0];
    const float* intervals = (const float*)d_in[1];
    const float* W_time    = (const float*)d_in[2];
    const float* b_time    = (const float*)d_in[3];
    const float* W_ih      = (const float*)d_in[4];
    const float* W_hh      = (const float*)d_in[5];
    const float* b_ih      = (const float*)d_in[6];
    const float* b_hh      = (const float*)d_in[7];
    const int*   lens      = (const int*)d_in[8];
    float* out = (float*)d_out;

    coef_kernel<<<(G3 + 255) / 256, 256>>>(W_time, b_time, W_ih, b_ih);

    dim3 ggrid(G3 / BN, NTOK / BM);   // (12, 64)
    gemm_kernel<<<ggrid, 256>>>(visit_emb, W_ih, intervals);

    cudaFuncSetAttribute(scan_kernel, cudaFuncAttributeNonPortableClusterSizeAllowed, 1);

    cudaLaunchConfig_t cfg = {};
    cfg.gridDim  = dim3(16, 1, 1);
    cfg.blockDim = dim3(512, 1, 1);
    cfg.dynamicSmemBytes = 0;
    cfg.stream = 0;
    cudaLaunchAttribute attrs[1];
    attrs[0].id = cudaLaunchAttributeClusterDimension;
    attrs[0].val.clusterDim.x = 16;
    attrs[0].val.clusterDim.y = 1;
    attrs[0].val.clusterDim.z = 1;
    cfg.attrs = attrs;
    cfg.numAttrs = 1;

    cudaLaunchKernelEx(&cfg, scan_kernel, W_hh, b_hh, lens, out);
}